// round 1
// baseline (speedup 1.0000x reference)
#include <cuda_runtime.h>
#include <math.h>

#define B_ 16
#define N_ 512
#define H_ 8
#define E_ 128
#define BH_ (B_*H_)
#define NEGV (-1000000000.0f)

// Intermediates in device globals (no runtime allocation allowed).
// Layout: [B, H, N, E] row-major, i.e. [(b*H+h)*N + n]*E + e
__device__ float g_q[BH_*N_*E_];
__device__ float g_k[BH_*N_*E_];
__device__ float g_v[BH_*N_*E_];
__device__ float g_y[BH_*N_*E_];

// ---------------------------------------------------------------------------
// Kernel 1: fused QKV projection.  C[8192,1024] = X[8192,128] @ W^T + b
// blockIdx.z selects q/k/v.  64x64 tile, 256 threads, 4x4 micro-tile.
// ---------------------------------------------------------------------------
__global__ __launch_bounds__(256) void qkv_kernel(
    const float* __restrict__ x,
    const float* __restrict__ Wq, const float* __restrict__ bq,
    const float* __restrict__ Wk, const float* __restrict__ bk,
    const float* __restrict__ Wv, const float* __restrict__ bv)
{
    const int which = blockIdx.z;
    const float* __restrict__ W    = (which == 0) ? Wq : (which == 1) ? Wk : Wv;
    const float* __restrict__ bias = (which == 0) ? bq : (which == 1) ? bk : bv;
    float* __restrict__ out        = (which == 0) ? g_q : (which == 1) ? g_k : g_v;

    __shared__ float xs[64][68];   // [e][row], pad 68 for float4-aligned, conflict-free reads
    __shared__ float ws[64][68];   // [e][col]

    const int tid  = threadIdx.x;
    const int ty   = tid >> 4;          // 0..15 -> 4 rows each
    const int tx   = tid & 15;          // 0..15 -> 4 cols each
    const int row0 = blockIdx.x << 6;   // 128 blocks over 8192 rows
    const int col0 = blockIdx.y << 6;   // 16 blocks over 1024 cols

    float acc[4][4] = {};

    for (int e0 = 0; e0 < 128; e0 += 64) {
        #pragma unroll
        for (int i = 0; i < 16; i++) {
            int idx = tid + (i << 8);
            int r = idx >> 6, e = idx & 63;
            xs[e][r] = x[(row0 + r) * E_ + e0 + e];
        }
        #pragma unroll
        for (int i = 0; i < 16; i++) {
            int idx = tid + (i << 8);
            int c = idx >> 6, e = idx & 63;
            ws[e][c] = W[(col0 + c) * E_ + e0 + e];
        }
        __syncthreads();
        #pragma unroll 8
        for (int e = 0; e < 64; e++) {
            float4 av = *(const float4*)&xs[e][ty << 2];
            float4 wv = *(const float4*)&ws[e][tx << 2];
            float a[4] = {av.x, av.y, av.z, av.w};
            float w[4] = {wv.x, wv.y, wv.z, wv.w};
            #pragma unroll
            for (int i = 0; i < 4; i++)
                #pragma unroll
                for (int j = 0; j < 4; j++)
                    acc[i][j] += a[i] * w[j];
        }
        __syncthreads();
    }

    const int col = col0 + (tx << 2);
    const int h = col >> 7, e = col & 127;      // col within 1024 = h*128+e
    float4 bv4 = *(const float4*)&bias[col];
    #pragma unroll
    for (int i = 0; i < 4; i++) {
        int row = row0 + (ty << 2) + i;
        int b = row >> 9, n = row & 511;
        float4 o = make_float4(acc[i][0] + bv4.x, acc[i][1] + bv4.y,
                               acc[i][2] + bv4.z, acc[i][3] + bv4.w);
        *(float4*)&out[((size_t)((b * H_ + h) * N_ + n) << 7) + e] = o;
    }
}

// ---------------------------------------------------------------------------
// Kernel 2: attention for one (b,h) and 32 queries per block.
// Full 512-key score row in smem -> exact softmax -> P@V.
// Dynamic smem layout (floats):
//   qs  [128][36]   (Q transposed, e-major)        4608
//   kvs [128][132]  (K transposed / V natural)    16896
//   ss  [32][520]   (scores/probs)                16640
//   mk  [512]       (key mask row)                  512
// total = 38656 floats = 154624 bytes
// ---------------------------------------------------------------------------
#define SMEM_ATTN_BYTES 154624

__global__ __launch_bounds__(256) void attn_kernel(
    const float* __restrict__ dist, const float* __restrict__ mask)
{
    extern __shared__ float sm[];
    float* qs  = sm;                    // stride 36
    float* kvs = sm + 128 * 36;        // stride 132
    float* ss  = kvs + 128 * 132;      // stride 520
    float* mk  = ss + 32 * 520;

    const int tid = threadIdx.x;
    const int bh  = blockIdx.y;        // 0..127
    const int b   = bh >> 3;
    const int q0  = blockIdx.x << 5;   // 16 q-tiles of 32

    const float* __restrict__ Q = g_q + (size_t)bh * N_ * E_;
    const float* __restrict__ K = g_k + (size_t)bh * N_ * E_;
    const float* __restrict__ V = g_v + (size_t)bh * N_ * E_;

    // key mask row
    for (int i = tid; i < 512; i += 256) mk[i] = mask[b * 512 + i];

    // load Q tile transposed: 32 rows x 128 e
    #pragma unroll
    for (int i = 0; i < 16; i++) {
        int idx = tid + (i << 8);
        int r = idx >> 7, e = idx & 127;
        qs[e * 36 + r] = Q[(q0 + r) * E_ + e];
    }
    __syncthreads();

    const int ty = tid >> 5;    // 0..7 -> 4 query rows each (32 rows)
    const int tx = tid & 31;    // 0..31 -> 4 key cols each (128 cols)
    const float scale = 0.0883883476483184f;  // 128^-0.5

    // ---- Phase 1: S = scale*(Q K^T) + dist, key-masked, into ss ----
    for (int kt = 0; kt < 4; kt++) {
        #pragma unroll
        for (int i = 0; i < 64; i++) {
            int idx = tid + (i << 8);
            int r = idx >> 7, e = idx & 127;
            kvs[e * 132 + r] = K[(kt * 128 + r) * E_ + e];
        }
        __syncthreads();

        float acc[4][4] = {};
        #pragma unroll 8
        for (int e = 0; e < 128; e++) {
            float4 qv = *(const float4*)&qs[e * 36 + (ty << 2)];
            float4 kv = *(const float4*)&kvs[e * 132 + (tx << 2)];
            float a[4] = {qv.x, qv.y, qv.z, qv.w};
            float c[4] = {kv.x, kv.y, kv.z, kv.w};
            #pragma unroll
            for (int i = 0; i < 4; i++)
                #pragma unroll
                for (int j = 0; j < 4; j++)
                    acc[i][j] += a[i] * c[j];
        }

        const int kbase = kt * 128 + (tx << 2);
        float m0 = mk[kbase + 0], m1 = mk[kbase + 1], m2 = mk[kbase + 2], m3 = mk[kbase + 3];
        #pragma unroll
        for (int i = 0; i < 4; i++) {
            int qg = q0 + (ty << 2) + i;
            float4 dv = *(const float4*)&dist[((size_t)b * N_ + qg) * N_ + kbase];
            float4 s;
            s.x = (m0 != 0.f) ? acc[i][0] * scale + dv.x : NEGV;
            s.y = (m1 != 0.f) ? acc[i][1] * scale + dv.y : NEGV;
            s.z = (m2 != 0.f) ? acc[i][2] * scale + dv.z : NEGV;
            s.w = (m3 != 0.f) ? acc[i][3] * scale + dv.w : NEGV;
            *(float4*)&ss[((ty << 2) + i) * 520 + kbase] = s;
        }
        __syncthreads();
    }

    // ---- Phase 2: row softmax (8 warps x 4 rows) ----
    {
        const int warp = tid >> 5, lane = tid & 31;
        #pragma unroll
        for (int rr = 0; rr < 4; rr++) {
            int r = (warp << 2) + rr;
            float m = NEGV;
            for (int j = lane; j < 512; j += 32) m = fmaxf(m, ss[r * 520 + j]);
            #pragma unroll
            for (int o = 16; o; o >>= 1) m = fmaxf(m, __shfl_xor_sync(0xffffffff, m, o));
            float l = 0.f;
            for (int j = lane; j < 512; j += 32) {
                float p = __expf(ss[r * 520 + j] - m);
                ss[r * 520 + j] = p;
                l += p;
            }
            #pragma unroll
            for (int o = 16; o; o >>= 1) l += __shfl_xor_sync(0xffffffff, l, o);
            float inv = 1.f / l;
            for (int j = lane; j < 512; j += 32) ss[r * 520 + j] *= inv;
        }
    }
    __syncthreads();

    // ---- Phase 3: Y = P @ V ----
    float acc2[4][4] = {};
    for (int kt = 0; kt < 4; kt++) {
        // load V tile natural layout [key][e], float4
        #pragma unroll
        for (int i = 0; i < 16; i++) {
            int idx = tid + (i << 8);        // 4096 float4 slots
            int key = idx >> 5, e4 = idx & 31;
            float4 vv = *(const float4*)&V[(kt * 128 + key) * E_ + (e4 << 2)];
            *(float4*)&kvs[key * 132 + (e4 << 2)] = vv;
        }
        __syncthreads();

        #pragma unroll 4
        for (int kk = 0; kk < 128; kk++) {
            int c = kt * 128 + kk;
            float p0 = ss[((ty << 2) + 0) * 520 + c];
            float p1 = ss[((ty << 2) + 1) * 520 + c];
            float p2 = ss[((ty << 2) + 2) * 520 + c];
            float p3 = ss[((ty << 2) + 3) * 520 + c];
            float4 vv = *(const float4*)&kvs[kk * 132 + (tx << 2)];
            acc2[0][0] += p0 * vv.x; acc2[0][1] += p0 * vv.y; acc2[0][2] += p0 * vv.z; acc2[0][3] += p0 * vv.w;
            acc2[1][0] += p1 * vv.x; acc2[1][1] += p1 * vv.y; acc2[1][2] += p1 * vv.z; acc2[1][3] += p1 * vv.w;
            acc2[2][0] += p2 * vv.x; acc2[2][1] += p2 * vv.y; acc2[2][2] += p2 * vv.z; acc2[2][3] += p2 * vv.w;
            acc2[3][0] += p3 * vv.x; acc2[3][1] += p3 * vv.y; acc2[3][2] += p3 * vv.z; acc2[3][3] += p3 * vv.w;
        }
        __syncthreads();
    }

    float* __restrict__ Y = g_y + (size_t)bh * N_ * E_;
    #pragma unroll
    for (int i = 0; i < 4; i++) {
        int qg = q0 + (ty << 2) + i;
        *(float4*)&Y[qg * E_ + (tx << 2)] =
            make_float4(acc2[i][0], acc2[i][1], acc2[i][2], acc2[i][3]);
    }
}

// ---------------------------------------------------------------------------
// Kernel 3: out[8192,128] = Y[8192,1024] @ Wo^T + bo, then * mask[b,n]
// 64x64 tiles, K chunks of 64 (each chunk within one head).
// ---------------------------------------------------------------------------
__global__ __launch_bounds__(256) void oproj_kernel(
    const float* __restrict__ Wo, const float* __restrict__ bo,
    const float* __restrict__ mask, float* __restrict__ out)
{
    __shared__ float as_[64][68];
    __shared__ float ws_[64][68];

    const int tid  = threadIdx.x;
    const int ty   = tid >> 4;
    const int tx   = tid & 15;
    const int row0 = blockIdx.x << 6;   // 128 blocks over 8192 rows
    const int col0 = blockIdx.y << 6;   // 2 blocks over 128 cols

    float acc[4][4] = {};

    for (int k0 = 0; k0 < 1024; k0 += 64) {
        const int h = k0 >> 7;
        const int eoff = k0 & 127;
        #pragma unroll
        for (int i = 0; i < 16; i++) {
            int idx = tid + (i << 8);
            int r = idx >> 6, kk = idx & 63;
            int row = row0 + r;
            int b = row >> 9, n = row & 511;
            as_[kk][r] = g_y[((size_t)((b * H_ + h) * N_ + n) << 7) + eoff + kk];
        }
        #pragma unroll
        for (int i = 0; i < 16; i++) {
            int idx = tid + (i << 8);
            int c = idx >> 6, kk = idx & 63;
            ws_[kk][c] = Wo[(col0 + c) * 1024 + k0 + kk];
        }
        __syncthreads();
        #pragma unroll 8
        for (int kk = 0; kk < 64; kk++) {
            float4 av = *(const float4*)&as_[kk][ty << 2];
            float4 wv = *(const float4*)&ws_[kk][tx << 2];
            float a[4] = {av.x, av.y, av.z, av.w};
            float w[4] = {wv.x, wv.y, wv.z, wv.w};
            #pragma unroll
            for (int i = 0; i < 4; i++)
                #pragma unroll
                for (int j = 0; j < 4; j++)
                    acc[i][j] += a[i] * w[j];
        }
        __syncthreads();
    }

    float4 bv4 = *(const float4*)&bo[col0 + (tx << 2)];
    #pragma unroll
    for (int i = 0; i < 4; i++) {
        int row = row0 + (ty << 2) + i;
        int b = row >> 9, n = row & 511;
        float mv = mask[b * 512 + n];
        float4 o = make_float4((acc[i][0] + bv4.x) * mv, (acc[i][1] + bv4.y) * mv,
                               (acc[i][2] + bv4.z) * mv, (acc[i][3] + bv4.w) * mv);
        *(float4*)&out[(size_t)row * E_ + col0 + (tx << 2)] = o;
    }
}

// ---------------------------------------------------------------------------
extern "C" void kernel_launch(void* const* d_in, const int* in_sizes, int n_in,
                              void* d_out, int out_size)
{
    const float* x    = (const float*)d_in[0];
    const float* dist = (const float*)d_in[1];
    const float* mask = (const float*)d_in[2];
    const float* Wq   = (const float*)d_in[3];
    const float* bq   = (const float*)d_in[4];
    const float* Wk   = (const float*)d_in[5];
    const float* bk   = (const float*)d_in[6];
    const float* Wv   = (const float*)d_in[7];
    const float* bv   = (const float*)d_in[8];
    const float* Wo   = (const float*)d_in[9];
    const float* bo   = (const float*)d_in[10];
    float* out = (float*)d_out;

    cudaFuncSetAttribute(attn_kernel,
                         cudaFuncAttributeMaxDynamicSharedMemorySize,
                         SMEM_ATTN_BYTES);

    qkv_kernel<<<dim3(128, 16, 3), 256>>>(x, Wq, bq, Wk, bk, Wv, bv);
    attn_kernel<<<dim3(16, 128), 256, SMEM_ATTN_BYTES>>>(dist, mask);
    oproj_kernel<<<dim3(128, 2), 256>>>(Wo, bo, mask, out);
}